// round 8
// baseline (speedup 1.0000x reference)
#include <cuda_runtime.h>
#include <cstdint>

#define NB      16         // batch
#define C       256        // channels
#define CH      128        // C/2 hidden / selected count
#define HW      16384      // 128*128 spatial
#define HW4     4096       // HW / 4 (float4)
#define CHUNK_B 2          // batches per chunk (32 MB) -> chunk k + k-1 fit L2
#define NCHUNK  (NB / CHUNK_B)        // 8
#define CTASKS  (CHUNK_B * C)         // 512 channel-tasks per chunk
#define GRID    592        // 148 SMs x 4 blocks; guaranteed co-resident
#define GMEAN   280        // mean-group size in mixed phases (rest: scatter)

__device__ float g_z[NB * C];     // channel means
__device__ int   g_dst[NB * C];   // channel c -> output slot
__device__ int   g_flag[NB];      // per-batch "ranks ready" flags
__device__ int   g_cnt;           // barrier arrival counter (self-resetting)
__device__ int   g_gen;           // barrier generation     (self-resetting)

// ---------------------------------------------------------------------------
// Grid-wide sense-reversing barrier. Safe because all GRID blocks are
// co-resident (grid = 148x4, launch_bounds(256,4)). Fully self-resetting.
// ---------------------------------------------------------------------------
__device__ __forceinline__ void grid_barrier(bool final_reset)
{
    __syncthreads();
    if (threadIdx.x == 0) {
        int my = atomicAdd(&g_gen, 0);
        __threadfence();                       // release my writes
        int old = atomicAdd(&g_cnt, 1);
        if (old == GRID - 1) {
            if (final_reset)
                for (int i = 0; i < NB; ++i) g_flag[i] = 0;
            atomicExch(&g_cnt, 0);
            __threadfence();
            atomicExch(&g_gen, final_reset ? 0 : my + 1);
        } else {
            while (atomicAdd(&g_gen, 0) == my) __nanosleep(128);
        }
        __threadfence();                       // acquire others' writes
    }
    __syncthreads();
}

// ---------------------------------------------------------------------------
__device__ __forceinline__ void prefetch_l2(const void* p, int bytes)
{
    const char* c = (const char*)p;
    for (int i = threadIdx.x * 128; i < bytes; i += 256 * 128)
        asm volatile("prefetch.global.L2 [%0];" :: "l"(c + i));
}

// ---------------------------------------------------------------------------
// Channel mean for one (n,c). Bit-identical math to the passing R6 kernel.
// ---------------------------------------------------------------------------
__device__ __forceinline__ void mean_task(const float* __restrict__ x, int nc)
{
    const float4* __restrict__ p =
        reinterpret_cast<const float4*>(x + (size_t)nc * HW);
    float s = 0.0f;
    #pragma unroll
    for (int k = 0; k < HW4 / 256; ++k) {
        float4 v = p[threadIdx.x + k * 256];
        s += (v.x + v.y) + (v.z + v.w);
    }
    #pragma unroll
    for (int o = 16; o > 0; o >>= 1)
        s += __shfl_xor_sync(0xFFFFFFFFu, s, o);

    __shared__ float red[8];
    const int lane = threadIdx.x & 31, wid = threadIdx.x >> 5;
    if (lane == 0) red[wid] = s;
    __syncthreads();
    if (threadIdx.x == 0) {
        float t = 0.0f;
        #pragma unroll
        for (int w = 0; w < 8; ++w) t += red[w];
        g_z[nc] = t * (1.0f / (float)HW);
    }
    __syncthreads();                 // red[] reuse across tasks
}

// ---------------------------------------------------------------------------
// MLP + sigmoid + stable rank for batch n (whole block). Identical math to R6.
// ---------------------------------------------------------------------------
__device__ void mlp_task(int n,
    const float* __restrict__ W1, const float* __restrict__ b1,
    const float* __restrict__ W2, const float* __restrict__ b2)
{
    const int t    = threadIdx.x;
    const int lane = t & 31;
    const int wid  = t >> 5;

    __shared__ __align__(16) float z[C];
    __shared__ __align__(16) float h[CH];
    __shared__ float sc[C];

    z[t] = __ldcg(&g_z[n * C + t]);            // L2 read (cross-SM fresh)
    __syncthreads();

    const float4* __restrict__ z4 = reinterpret_cast<const float4*>(z);

    #pragma unroll
    for (int ii = 0; ii < 16; ++ii) {
        const int i = wid * 16 + ii;
        const float4* __restrict__ w4 =
            reinterpret_cast<const float4*>(W1 + i * C);
        float4 wa = w4[lane], wb = w4[lane + 32];
        float4 za = z4[lane], zb = z4[lane + 32];
        float a = wa.x * za.x;
        a = fmaf(wa.y, za.y, a); a = fmaf(wa.z, za.z, a); a = fmaf(wa.w, za.w, a);
        a = fmaf(wb.x, zb.x, a); a = fmaf(wb.y, zb.y, a);
        a = fmaf(wb.z, zb.z, a); a = fmaf(wb.w, zb.w, a);
        #pragma unroll
        for (int o = 16; o > 0; o >>= 1)
            a += __shfl_xor_sync(0xFFFFFFFFu, a, o);
        if (lane == 0) {
            float v = a + b1[i];
            h[i] = v > 0.0f ? v : 0.0f;
        }
    }
    __syncthreads();

    const float4* __restrict__ h4 = reinterpret_cast<const float4*>(h);

    #pragma unroll
    for (int ii = 0; ii < 32; ++ii) {
        const int i = wid * 32 + ii;
        const float4* __restrict__ w4 =
            reinterpret_cast<const float4*>(W2 + i * CH);
        float4 wa = w4[lane];
        float4 ha = h4[lane];
        float a = wa.x * ha.x;
        a = fmaf(wa.y, ha.y, a); a = fmaf(wa.z, ha.z, a); a = fmaf(wa.w, ha.w, a);
        #pragma unroll
        for (int o = 16; o > 0; o >>= 1)
            a += __shfl_xor_sync(0xFFFFFFFFu, a, o);
        if (lane == 0)
            sc[i] = 1.0f / (1.0f + expf(-(a + b2[i])));
    }
    __syncthreads();

    // Stable descending rank (matches jnp.argsort(-scores))
    const float mys = sc[t];
    int rank = 0;
    #pragma unroll 8
    for (int j = 0; j < C; ++j) {
        float sj = sc[j];
        rank += (sj > mys) || (sj == mys && j < t);
    }
    g_dst[n * C + t] = rank;
    __syncthreads();
    if (t == 0) {
        __threadfence();                        // release g_dst
        atomicExch(&g_flag[n], 1);
    }
}

// ---------------------------------------------------------------------------
// Scatter one channel (linear L2-warm read, permuted streaming write).
// ---------------------------------------------------------------------------
__device__ __forceinline__ void scatter_task(
    const float* __restrict__ x, float* __restrict__ out, int b)
{
    const int n    = b >> 8;
    const int slot = __ldcg(&g_dst[b]);

    const float4* __restrict__ src =
        reinterpret_cast<const float4*>(x + (size_t)b * HW);

    size_t dst_ch;
    if (slot < CH) dst_ch = (size_t)n * CH + slot;                          // selected
    else           dst_ch = (size_t)NB * CH + (size_t)n * CH + (slot - CH); // remaining
    float4* __restrict__ dst = reinterpret_cast<float4*>(out + dst_ch * HW);

    #pragma unroll
    for (int half = 0; half < 2; ++half) {
        const int off = half * (HW4 / 2) + threadIdx.x;
        float4 r[8];
        #pragma unroll
        for (int k = 0; k < 8; ++k)
            r[k] = src[off + k * 256];
        #pragma unroll
        for (int k = 0; k < 8; ++k)
            __stcs(&dst[off + k * 256], r[k]);
    }
}

// ---------------------------------------------------------------------------
// Persistent fused kernel: phase p runs mean(chunk p) on one block-group and
// scatter(chunk p-1) on the other, separated by grid barriers. Mixing the
// read and write streams + L2 chunk reuse removes the second DRAM read of x.
// ---------------------------------------------------------------------------
__global__ __launch_bounds__(256, 4) void fused_kernel(
    const float* __restrict__ x,
    const float* __restrict__ W1, const float* __restrict__ b1,
    const float* __restrict__ W2, const float* __restrict__ b2,
    float* __restrict__ out)
{
    const int bid = blockIdx.x;

    for (int p = 0; p <= NCHUNK; ++p) {
        const bool has_mean = (p < NCHUNK);
        const bool has_scat = (p > 0);
        const int  gm = has_scat ? (has_mean ? GMEAN : 0) : GRID;

        if (has_mean && bid < gm) {
            if (p == 0 && bid < 2)              // warm weights into L2
                prefetch_l2(bid == 0 ? (const void*)W1 : (const void*)W2,
                            CH * C * 4);
            const int base = p * CTASKS;
            for (int t = bid; t < CTASKS; t += gm)
                mean_task(x, base + t);
        } else if (has_scat) {
            const int srank = bid - gm, ssz = GRID - gm;
            const int ck = p - 1, b0 = ck * CHUNK_B;

            if (srank < CHUNK_B)                // one block per batch: ranks
                mlp_task(b0 + srank, W1, b1, W2, b2);

            // prefetch first task's channel into L2 while waiting for ranks
            if (srank < CTASKS) {
                const char* sp = (const char*)(x +
                    (size_t)(ck * CTASKS + srank) * HW) + threadIdx.x * 256;
                asm volatile("prefetch.global.L2 [%0];"     :: "l"(sp));
                asm volatile("prefetch.global.L2 [%0+128];" :: "l"(sp));
            }
            if (threadIdx.x == 0) {
                #pragma unroll
                for (int b = 0; b < CHUNK_B; ++b)
                    while (atomicAdd(&g_flag[b0 + b], 0) == 0) __nanosleep(64);
            }
            __syncthreads();

            for (int t = srank; t < CTASKS; t += ssz)
                scatter_task(x, out, ck * CTASKS + t);
        }

        grid_barrier(p == NCHUNK);
    }
}

// ---------------------------------------------------------------------------
extern "C" void kernel_launch(void* const* d_in, const int* in_sizes, int n_in,
                              void* d_out, int out_size)
{
    const float* x  = (const float*)d_in[0];
    const float* W1 = (const float*)d_in[1];
    const float* b1 = (const float*)d_in[2];
    const float* W2 = (const float*)d_in[3];
    const float* b2 = (const float*)d_in[4];
    float* out = (float*)d_out;

    fused_kernel<<<GRID, 256>>>(x, W1, b1, W2, b2, out);
}